// round 5
// baseline (speedup 1.0000x reference)
#include <cuda_runtime.h>

#define H   4096
#define IN  512
#define OUT 64

#define NKB 256            // k-dim split for k_recur
#define KR  (H / NKB)      // 16 rows per k-block
#define NJ4 (H / 4)        // 1024 float4 columns

// Device-global scratch. g_part layout: [kb][j4] as float4 (coalesced stores).
__device__ float4 g_part[(size_t)NKB * NJ4];   // 4 MB
__device__ float  g_x[H];

// ---------------------------------------------------------------------------
// Kernel 1: partial GEMV. Block (bx, kb): j4 in [bx*256, +256), rows
// [kb*16, +16). Grid (4, 256) = 1024 blocks x 256 threads.
// g_part[kb][j4] = sum_{k in slice} hidden[k] * (w[k][:] + plas*hebb) (float4)
// ---------------------------------------------------------------------------
__global__ void __launch_bounds__(256, 6)
k_recur(const float* __restrict__ hidden,
        const float* __restrict__ hebb,
        const float* __restrict__ w,
        const float* __restrict__ plas) {
    int j4 = blockIdx.x * 256 + threadIdx.x;   // float4 column index
    int kb = blockIdx.y;
    int k0 = kb * KR;

    const float4* w4 = (const float4*)w;
    const float4* p4 = (const float4*)plas;
    const float4* h4 = (const float4*)hebb;

    float4 acc = make_float4(0.f, 0.f, 0.f, 0.f);
    size_t base = (size_t)k0 * NJ4 + j4;
#pragma unroll 8
    for (int k = 0; k < KR; ++k, base += NJ4) {
        float hk = __ldg(hidden + k0 + k);
        float4 a = w4[base];
        float4 b = p4[base];
        float4 c = h4[base];
        acc.x += hk * fmaf(b.x, c.x, a.x);
        acc.y += hk * fmaf(b.y, c.y, a.y);
        acc.z += hk * fmaf(b.z, c.z, a.z);
        acc.w += hk * fmaf(b.w, c.w, a.w);
    }
    g_part[(size_t)kb * NJ4 + j4] = acc;   // fully coalesced
}

// ---------------------------------------------------------------------------
// Kernel 2 (fused): warp per j4 (4 output columns).
//   x[j] = relu( b[j] + dot(inp, W_i2h[j,:]) + sum_kb g_part[kb][j4].comp )
// 1024 warps = 128 blocks x 256 threads.
// ---------------------------------------------------------------------------
__global__ void __launch_bounds__(256)
k_reduce(const float* __restrict__ inp,
         const float* __restrict__ W_i2h,
         const float* __restrict__ b_i2h,
         float* __restrict__ x_out) {
    int warp = (blockIdx.x * blockDim.x + threadIdx.x) >> 5;  // j4 index
    int lane = threadIdx.x & 31;
    if (warp >= NJ4) return;

    // recurrent partials: lane sums kb = lane, lane+32, ... (8 iters)
    float4 part = make_float4(0.f, 0.f, 0.f, 0.f);
#pragma unroll
    for (int t = 0; t < NKB / 32; ++t) {
        float4 v = g_part[(size_t)(lane + t * 32) * NJ4 + warp];
        part.x += v.x; part.y += v.y; part.z += v.z; part.w += v.w;
    }

    // i2h dots for the 4 columns j = warp*4 + i
    const float4* in4 = (const float4*)inp;
    float tot[4] = {part.x, part.y, part.z, part.w};
#pragma unroll
    for (int i = 0; i < 4; ++i) {
        const float4* row = (const float4*)(W_i2h + ((size_t)warp * 4 + i) * IN);
        float acc = 0.f;
#pragma unroll
        for (int t = 0; t < (IN / 4) / 32; ++t) {
            float4 a = row[lane + t * 32];
            float4 b = in4[lane + t * 32];
            acc += a.x * b.x + a.y * b.y + a.z * b.z + a.w * b.w;
        }
        tot[i] += acc;
    }
#pragma unroll
    for (int i = 0; i < 4; ++i)
#pragma unroll
        for (int o = 16; o; o >>= 1)
            tot[i] += __shfl_down_sync(0xffffffffu, tot[i], o);

    if (lane == 0) {
#pragma unroll
        for (int i = 0; i < 4; ++i) {
            int j = warp * 4 + i;
            float v = fmaxf(tot[i] + b_i2h[j], 0.f);
            g_x[j]   = v;
            x_out[j] = v;
        }
    }
}

// ---------------------------------------------------------------------------
// Kernel 3 (fused): hebb update + output head.
//   hebb_new[k][j] = (1-learn)*hebb[k][j] + learn*hidden[k]*x[j]
// Rows reversed within each KR-stripe (read LRU-freshest L2 lines first).
// Blocks 0..63 additionally compute out[o] = tanh(dot(x, W_h2o[o,:]) + b).
// ---------------------------------------------------------------------------
__global__ void __launch_bounds__(256)
k_hebb_out(const float* __restrict__ hidden,
           const float* __restrict__ hebb,
           const float* __restrict__ learn_p,
           const float* __restrict__ W_h2o,
           const float* __restrict__ b_h2o,
           float* __restrict__ hebb_out,
           float* __restrict__ out) {
    __shared__ float red[8];
    int tid = threadIdx.x;

    if (blockIdx.x < OUT) {
        int o = blockIdx.x;
        const float4* wr = (const float4*)(W_h2o + (size_t)o * H);
        const float4* xv = (const float4*)g_x;
        float acc = 0.f;
#pragma unroll
        for (int t = 0; t < (H / 4) / 256; ++t) {
            int idx = tid + t * 256;
            float4 a = wr[idx];
            float4 b = xv[idx];
            acc += a.x * b.x + a.y * b.y + a.z * b.z + a.w * b.w;
        }
#pragma unroll
        for (int s = 16; s; s >>= 1) acc += __shfl_down_sync(0xffffffffu, acc, s);
        if ((tid & 31) == 0) red[tid >> 5] = acc;
        __syncthreads();
        if (tid == 0) {
            float v = red[0] + red[1] + red[2] + red[3] +
                      red[4] + red[5] + red[6] + red[7];
            out[o] = tanhf(v + b_h2o[o]);
        }
    }

    // ---- hebb update (all blocks) ----
    int idx = blockIdx.x * 256 + tid;       // float4 index over H*H/4
    int k   = idx >> 10;                    // row
    int jc  = idx & 1023;                   // float4 col
    int krev = (k & ~(KR - 1)) | ((KR - 1) - (k & (KR - 1)));
    size_t e = ((size_t)krev << 10) | jc;

    float learn = __ldg(learn_p);
    float hk    = __ldg(hidden + krev);
    float4 hb = ((const float4*)hebb)[e];
    float4 xv = ((const float4*)g_x)[jc];
    float a = 1.f - learn;
    float s = learn * hk;
    float4 o4;
    o4.x = fmaf(a, hb.x, s * xv.x);
    o4.y = fmaf(a, hb.y, s * xv.y);
    o4.z = fmaf(a, hb.z, s * xv.z);
    o4.w = fmaf(a, hb.w, s * xv.w);
    __stcs((float4*)hebb_out + e, o4);
}

// ---------------------------------------------------------------------------
// Inputs: 0 inp, 1 hidden, 2 hebb, 3 W_i2h, 4 b_i2h, 5 w, 6 plas,
//         7 learn, 8 W_h2o, 9 b_h2o
// Output: [out(64) | x(4096) | hebb_new(16777216)]
// ---------------------------------------------------------------------------
extern "C" void kernel_launch(void* const* d_in, const int* in_sizes, int n_in,
                              void* d_out, int out_size) {
    const float* inp    = (const float*)d_in[0];
    const float* hidden = (const float*)d_in[1];
    const float* hebb   = (const float*)d_in[2];
    const float* W_i2h  = (const float*)d_in[3];
    const float* b_i2h  = (const float*)d_in[4];
    const float* w      = (const float*)d_in[5];
    const float* plas   = (const float*)d_in[6];
    const float* learn  = (const float*)d_in[7];
    const float* W_h2o  = (const float*)d_in[8];
    const float* b_h2o  = (const float*)d_in[9];

    float* out      = (float*)d_out;
    float* x_out    = out + OUT;
    float* hebb_out = out + OUT + H;

    dim3 g1(NJ4 / 256, NKB);   // (4, 256) = 1024 blocks
    k_recur<<<g1, 256>>>(hidden, hebb, w, plas);

    k_reduce<<<(NJ4 * 32) / 256, 256>>>(inp, W_i2h, b_i2h, x_out);

    int n4 = (H * H) / 4;
    k_hebb_out<<<n4 / 256, 256>>>(hidden, hebb, learn, W_h2o, b_h2o,
                                  hebb_out, out);
}

// round 6
// speedup vs baseline: 1.0221x; 1.0221x over previous
#include <cuda_runtime.h>

#define H   4096
#define IN  512
#define OUT 64

#define NKB 256            // k-dim split for k_recur
#define KR  (H / NKB)      // 16 rows per k-block
#define NJ4 (H / 4)        // 1024 float4 columns

// Device-global scratch. g_part layout: [kb][j4] as float4 (coalesced stores).
__device__ float4 g_part[(size_t)NKB * NJ4];   // 4 MB
__device__ float  g_x[H];

// ---------------------------------------------------------------------------
// Kernel 1: partial GEMV. Block (bx, kb): j4 in [bx*256, +256), rows
// [kb*16, +16). Grid (4, 256) = 1024 blocks x 256 threads.
// w/plas are read streaming (L2 evict-first) so hebb stays L2-resident for
// k_hebb_out. hebb read with default policy.
// ---------------------------------------------------------------------------
__global__ void __launch_bounds__(256, 6)
k_recur(const float* __restrict__ hidden,
        const float* __restrict__ hebb,
        const float* __restrict__ w,
        const float* __restrict__ plas) {
    int j4 = blockIdx.x * 256 + threadIdx.x;   // float4 column index
    int kb = blockIdx.y;
    int k0 = kb * KR;

    const float4* w4 = (const float4*)w;
    const float4* p4 = (const float4*)plas;
    const float4* h4 = (const float4*)hebb;

    float4 acc = make_float4(0.f, 0.f, 0.f, 0.f);
    size_t base = (size_t)k0 * NJ4 + j4;
#pragma unroll 8
    for (int k = 0; k < KR; ++k, base += NJ4) {
        float hk = __ldg(hidden + k0 + k);
        float4 a = __ldcs(w4 + base);   // evict-first: no reuse
        float4 b = __ldcs(p4 + base);   // evict-first: no reuse
        float4 c = h4[base];            // default: keep for k_hebb_out
        acc.x += hk * fmaf(b.x, c.x, a.x);
        acc.y += hk * fmaf(b.y, c.y, a.y);
        acc.z += hk * fmaf(b.z, c.z, a.z);
        acc.w += hk * fmaf(b.w, c.w, a.w);
    }
    g_part[(size_t)kb * NJ4 + j4] = acc;   // fully coalesced
}

// ---------------------------------------------------------------------------
// Kernel 2 (fused): x = relu(b + i2h + sum_kb partials).
// 128 blocks x 256 threads; block handles 8 float4 columns (32 scalar cols).
// Phase A reads g_part in 4x128B coalesced chunks; smem transpose; i2h dots
// one-per-(warp,step); final relu write.
// ---------------------------------------------------------------------------
__global__ void __launch_bounds__(256)
k_reduce(const float* __restrict__ inp,
         const float* __restrict__ W_i2h,
         const float* __restrict__ b_i2h,
         float* __restrict__ x_out) {
    __shared__ float4 sp[32][8];     // partial sums [grp][j4loc]
    __shared__ float  sdot[32];      // i2h dot per column
    __shared__ float4 stot[8];       // reduced partials per j4loc

    int tid    = threadIdx.x;
    int j4base = blockIdx.x * 8;

    // ---- Phase A: partial accumulation (coalesced) ----
    int j4loc = tid & 7;
    int grp   = tid >> 3;            // 0..31
    float4 acc = make_float4(0.f, 0.f, 0.f, 0.f);
#pragma unroll
    for (int t = 0; t < NKB / 32; ++t) {
        float4 v = g_part[(size_t)(grp + 32 * t) * NJ4 + j4base + j4loc];
        acc.x += v.x; acc.y += v.y; acc.z += v.z; acc.w += v.w;
    }
    sp[grp][j4loc] = acc;
    __syncthreads();

    // ---- Phase B: reduce 32 groups per j4loc ----
    if (tid < 8) {
        float4 t4 = make_float4(0.f, 0.f, 0.f, 0.f);
#pragma unroll
        for (int g = 0; g < 32; ++g) {
            float4 v = sp[g][tid];
            t4.x += v.x; t4.y += v.y; t4.z += v.z; t4.w += v.w;
        }
        stot[tid] = t4;
    }

    // ---- Phase C: i2h dots, warp w does columns w*4 .. w*4+3 ----
    int wrp  = tid >> 5;             // 0..7
    int lane = tid & 31;
    const float4* in4 = (const float4*)inp;
#pragma unroll
    for (int c = 0; c < 4; ++c) {
        int col = wrp * 4 + c;                       // 0..31 within block
        int j   = j4base * 4 + col;
        const float4* row = (const float4*)(W_i2h + (size_t)j * IN);
        float d = 0.f;
#pragma unroll
        for (int t = 0; t < (IN / 4) / 32; ++t) {    // 4 iters
            float4 a = __ldcs(row + lane + t * 32);
            float4 b = in4[lane + t * 32];
            d += a.x * b.x + a.y * b.y + a.z * b.z + a.w * b.w;
        }
#pragma unroll
        for (int o = 16; o; o >>= 1) d += __shfl_down_sync(0xffffffffu, d, o);
        if (lane == 0) sdot[col] = d;
    }
    __syncthreads();

    // ---- Phase D: combine + relu + write ----
    if (tid < 32) {
        int col   = tid;
        int jl    = col >> 2;
        int comp  = col & 3;
        float4 t4 = stot[jl];
        float part = (comp == 0) ? t4.x : (comp == 1) ? t4.y
                   : (comp == 2) ? t4.z : t4.w;
        int j = j4base * 4 + col;
        float v = fmaxf(part + sdot[col] + b_i2h[j], 0.f);
        g_x[j]   = v;
        x_out[j] = v;
    }
}

// ---------------------------------------------------------------------------
// Kernel 3 (fused): hebb update + output head.
//   hebb_new[k][j] = (1-learn)*hebb[k][j] + learn*hidden[k]*x[j]
// hebb read default (expect L2 hits — recur steered w/plas out of L2);
// output written streaming. Rows reversed within each KR-stripe.
// Blocks 0..63 additionally compute out[o] = tanh(dot(x, W_h2o[o,:]) + b).
// ---------------------------------------------------------------------------
__global__ void __launch_bounds__(256)
k_hebb_out(const float* __restrict__ hidden,
           const float* __restrict__ hebb,
           const float* __restrict__ learn_p,
           const float* __restrict__ W_h2o,
           const float* __restrict__ b_h2o,
           float* __restrict__ hebb_out,
           float* __restrict__ out) {
    __shared__ float red[8];
    int tid = threadIdx.x;

    if (blockIdx.x < OUT) {
        int o = blockIdx.x;
        const float4* wr = (const float4*)(W_h2o + (size_t)o * H);
        const float4* xv = (const float4*)g_x;
        float acc = 0.f;
#pragma unroll
        for (int t = 0; t < (H / 4) / 256; ++t) {
            int idx = tid + t * 256;
            float4 a = __ldcs(wr + idx);
            float4 b = xv[idx];
            acc += a.x * b.x + a.y * b.y + a.z * b.z + a.w * b.w;
        }
#pragma unroll
        for (int s = 16; s; s >>= 1) acc += __shfl_down_sync(0xffffffffu, acc, s);
        if ((tid & 31) == 0) red[tid >> 5] = acc;
        __syncthreads();
        if (tid == 0) {
            float v = red[0] + red[1] + red[2] + red[3] +
                      red[4] + red[5] + red[6] + red[7];
            out[o] = tanhf(v + b_h2o[o]);
        }
    }

    // ---- hebb update (all blocks) ----
    int idx = blockIdx.x * 256 + tid;       // float4 index over H*H/4
    int k   = idx >> 10;                    // row
    int jc  = idx & 1023;                   // float4 col
    int krev = (k & ~(KR - 1)) | ((KR - 1) - (k & (KR - 1)));
    size_t e = ((size_t)krev << 10) | jc;

    float learn = __ldg(learn_p);
    float hk    = __ldg(hidden + krev);
    float4 hb = ((const float4*)hebb)[e];       // expect L2 hit
    float4 xv = ((const float4*)g_x)[jc];
    float a = 1.f - learn;
    float s = learn * hk;
    float4 o4;
    o4.x = fmaf(a, hb.x, s * xv.x);
    o4.y = fmaf(a, hb.y, s * xv.y);
    o4.z = fmaf(a, hb.z, s * xv.z);
    o4.w = fmaf(a, hb.w, s * xv.w);
    __stcs((float4*)hebb_out + e, o4);
}

// ---------------------------------------------------------------------------
// Inputs: 0 inp, 1 hidden, 2 hebb, 3 W_i2h, 4 b_i2h, 5 w, 6 plas,
//         7 learn, 8 W_h2o, 9 b_h2o
// Output: [out(64) | x(4096) | hebb_new(16777216)]
// ---------------------------------------------------------------------------
extern "C" void kernel_launch(void* const* d_in, const int* in_sizes, int n_in,
                              void* d_out, int out_size) {
    const float* inp    = (const float*)d_in[0];
    const float* hidden = (const float*)d_in[1];
    const float* hebb   = (const float*)d_in[2];
    const float* W_i2h  = (const float*)d_in[3];
    const float* b_i2h  = (const float*)d_in[4];
    const float* w      = (const float*)d_in[5];
    const float* plas   = (const float*)d_in[6];
    const float* learn  = (const float*)d_in[7];
    const float* W_h2o  = (const float*)d_in[8];
    const float* b_h2o  = (const float*)d_in[9];

    float* out      = (float*)d_out;
    float* x_out    = out + OUT;
    float* hebb_out = out + OUT + H;

    dim3 g1(NJ4 / 256, NKB);   // (4, 256) = 1024 blocks
    k_recur<<<g1, 256>>>(hidden, hebb, w, plas);

    k_reduce<<<NJ4 / 8, 256>>>(inp, W_i2h, b_i2h, x_out);

    int n4 = (H * H) / 4;
    k_hebb_out<<<n4 / 256, 256>>>(hidden, hebb, learn, W_h2o, b_h2o,
                                  hebb_out, out);
}

// round 8
// speedup vs baseline: 1.0310x; 1.0087x over previous
#include <cuda_runtime.h>

#define H   4096
#define IN  512
#define OUT 64

#define GY  296            // k-blocks: 2*296 = 592 = 148 SM * 4 CTA (one wave)
#define NJ4 (H / 4)        // 1024 float4 columns
#define NJ8 (H / 8)        // 512  8-float columns

// Device-global scratch. g_part layout: [kb][j4] as float4 (coalesced stores).
__device__ float4 g_part[(size_t)GY * NJ4];   // ~4.9 MB
__device__ float  g_x[H];

// ---------------------------------------------------------------------------
// Kernel 1: partial GEMV, one full wave (592 blocks x 256 threads).
// Thread owns 8 consecutive floats (j8). hebb is read as one 32 B
// v8.b32 load with L2::evict_last (pins hebb in L2 for k_hebb_out);
// w/plas use plain float4 loads (ldcs measured to cost ~3 us here).
// ---------------------------------------------------------------------------
__global__ void __launch_bounds__(256)
k_recur(const float* __restrict__ hidden,
        const float* __restrict__ hebb,
        const float* __restrict__ w,
        const float* __restrict__ plas) {
    int j8 = blockIdx.x * 256 + threadIdx.x;   // 0..511
    int kb = blockIdx.y;
    int k0 = (kb * H) / GY;
    int k1 = ((kb + 1) * H) / GY;

    const float4* w4 = (const float4*)w;
    const float4* p4 = (const float4*)plas;
    const float4* h4 = (const float4*)hebb;

    float4 acc0 = make_float4(0.f, 0.f, 0.f, 0.f);
    float4 acc1 = make_float4(0.f, 0.f, 0.f, 0.f);
    size_t base = (size_t)k0 * NJ4 + j8 * 2;   // float4 index
#pragma unroll 4
    for (int k = k0; k < k1; ++k, base += NJ4) {
        float hk = __ldg(hidden + k);
        float4 a0 = w4[base], a1 = w4[base + 1];
        float4 b0 = p4[base], b1 = p4[base + 1];
        float4 c0, c1;
        asm volatile(
            "ld.global.nc.L2::evict_last.v8.b32 "
            "{%0,%1,%2,%3,%4,%5,%6,%7}, [%8];"
            : "=f"(c0.x), "=f"(c0.y), "=f"(c0.z), "=f"(c0.w),
              "=f"(c1.x), "=f"(c1.y), "=f"(c1.z), "=f"(c1.w)
            : "l"(h4 + base));
        acc0.x += hk * fmaf(b0.x, c0.x, a0.x);
        acc0.y += hk * fmaf(b0.y, c0.y, a0.y);
        acc0.z += hk * fmaf(b0.z, c0.z, a0.z);
        acc0.w += hk * fmaf(b0.w, c0.w, a0.w);
        acc1.x += hk * fmaf(b1.x, c1.x, a1.x);
        acc1.y += hk * fmaf(b1.y, c1.y, a1.y);
        acc1.z += hk * fmaf(b1.z, c1.z, a1.z);
        acc1.w += hk * fmaf(b1.w, c1.w, a1.w);
    }
    size_t o = (size_t)kb * NJ4 + j8 * 2;
    g_part[o]     = acc0;    // thread writes 32 contiguous bytes;
    g_part[o + 1] = acc1;    // warp covers 1 KB contiguous — coalesced
}

// ---------------------------------------------------------------------------
// Kernel 2 (fused): x = relu(b + i2h + sum_kb partials).
// 128 blocks x 256 threads; block handles 8 float4 columns (32 scalar cols).
// ---------------------------------------------------------------------------
__global__ void __launch_bounds__(256)
k_reduce(const float* __restrict__ inp,
         const float* __restrict__ W_i2h,
         const float* __restrict__ b_i2h,
         float* __restrict__ x_out) {
    __shared__ float4 sp[32][8];     // partial sums [grp][j4loc]
    __shared__ float  sdot[32];      // i2h dot per column
    __shared__ float4 stot[8];       // reduced partials per j4loc

    int tid    = threadIdx.x;
    int j4base = blockIdx.x * 8;

    // ---- Phase A: partial accumulation (coalesced reads of g_part) ----
    int j4loc = tid & 7;
    int grp   = tid >> 3;            // 0..31
    float4 acc = make_float4(0.f, 0.f, 0.f, 0.f);
#pragma unroll
    for (int t = 0; t < (GY + 31) / 32; ++t) {
        int kb = grp + 32 * t;
        if (kb < GY) {
            float4 v = g_part[(size_t)kb * NJ4 + j4base + j4loc];
            acc.x += v.x; acc.y += v.y; acc.z += v.z; acc.w += v.w;
        }
    }
    sp[grp][j4loc] = acc;
    __syncthreads();

    // ---- Phase B: reduce 32 groups per j4loc ----
    if (tid < 8) {
        float4 t4 = make_float4(0.f, 0.f, 0.f, 0.f);
#pragma unroll
        for (int g = 0; g < 32; ++g) {
            float4 v = sp[g][tid];
            t4.x += v.x; t4.y += v.y; t4.z += v.z; t4.w += v.w;
        }
        stot[tid] = t4;
    }

    // ---- Phase C: i2h dots, warp w does columns w*4 .. w*4+3 ----
    int wrp  = tid >> 5;             // 0..7
    int lane = tid & 31;
    const float4* in4 = (const float4*)inp;
#pragma unroll
    for (int c = 0; c < 4; ++c) {
        int col = wrp * 4 + c;                       // 0..31 within block
        int j   = j4base * 4 + col;
        const float4* row = (const float4*)(W_i2h + (size_t)j * IN);
        float d = 0.f;
#pragma unroll
        for (int t = 0; t < (IN / 4) / 32; ++t) {    // 4 iters
            float4 a = row[lane + t * 32];
            float4 b = in4[lane + t * 32];
            d += a.x * b.x + a.y * b.y + a.z * b.z + a.w * b.w;
        }
#pragma unroll
        for (int o = 16; o; o >>= 1) d += __shfl_down_sync(0xffffffffu, d, o);
        if (lane == 0) sdot[col] = d;
    }
    __syncthreads();

    // ---- Phase D: combine + relu + write ----
    if (tid < 32) {
        int col   = tid;
        int jl    = col >> 2;
        int comp  = col & 3;
        float4 t4 = stot[jl];
        float part = (comp == 0) ? t4.x : (comp == 1) ? t4.y
                   : (comp == 2) ? t4.z : t4.w;
        int j = j4base * 4 + col;
        float v = fmaxf(part + sdot[col] + b_i2h[j], 0.f);
        g_x[j]   = v;
        x_out[j] = v;
    }
}

// ---------------------------------------------------------------------------
// Kernel 3 (fused): hebb update + output head.
//   hebb_new[k][j] = (1-learn)*hebb[k][j] + learn*hidden[k]*x[j]
// hebb read expects L2 hits (evict_last residency from k_recur); output
// written streaming. Blocks 0..63 also compute out[o] = tanh(x.W_h2o[o]+b).
// ---------------------------------------------------------------------------
__global__ void __launch_bounds__(256)
k_hebb_out(const float* __restrict__ hidden,
           const float* __restrict__ hebb,
           const float* __restrict__ learn_p,
           const float* __restrict__ W_h2o,
           const float* __restrict__ b_h2o,
           float* __restrict__ hebb_out,
           float* __restrict__ out) {
    __shared__ float red[8];
    int tid = threadIdx.x;

    if (blockIdx.x < OUT) {
        int o = blockIdx.x;
        const float4* wr = (const float4*)(W_h2o + (size_t)o * H);
        const float4* xv = (const float4*)g_x;
        float acc = 0.f;
#pragma unroll
        for (int t = 0; t < (H / 4) / 256; ++t) {
            int idx = tid + t * 256;
            float4 a = wr[idx];
            float4 b = xv[idx];
            acc += a.x * b.x + a.y * b.y + a.z * b.z + a.w * b.w;
        }
#pragma unroll
        for (int s = 16; s; s >>= 1) acc += __shfl_down_sync(0xffffffffu, acc, s);
        if ((tid & 31) == 0) red[tid >> 5] = acc;
        __syncthreads();
        if (tid == 0) {
            float v = red[0] + red[1] + red[2] + red[3] +
                      red[4] + red[5] + red[6] + red[7];
            out[o] = tanhf(v + b_h2o[o]);
        }
    }

    // ---- hebb update (all blocks) ----
    int idx = blockIdx.x * 256 + tid;       // float4 index over H*H/4
    int k   = idx >> 10;                    // row
    int jc  = idx & 1023;                   // float4 col

    float learn = __ldg(learn_p);
    float hk    = __ldg(hidden + k);
    float4 hb = ((const float4*)hebb)[idx];     // expect L2 hit
    float4 xv = ((const float4*)g_x)[jc];
    float a = 1.f - learn;
    float s = learn * hk;
    float4 o4;
    o4.x = fmaf(a, hb.x, s * xv.x);
    o4.y = fmaf(a, hb.y, s * xv.y);
    o4.z = fmaf(a, hb.z, s * xv.z);
    o4.w = fmaf(a, hb.w, s * xv.w);
    __stcs((float4*)hebb_out + idx, o4);
}

// ---------------------------------------------------------------------------
// Inputs: 0 inp, 1 hidden, 2 hebb, 3 W_i2h, 4 b_i2h, 5 w, 6 plas,
//         7 learn, 8 W_h2o, 9 b_h2o
// Output: [out(64) | x(4096) | hebb_new(16777216)]
// ---------------------------------------------------------------------------
extern "C" void kernel_launch(void* const* d_in, const int* in_sizes, int n_in,
                              void* d_out, int out_size) {
    const float* inp    = (const float*)d_in[0];
    const float* hidden = (const float*)d_in[1];
    const float* hebb   = (const float*)d_in[2];
    const float* W_i2h  = (const float*)d_in[3];
    const float* b_i2h  = (const float*)d_in[4];
    const float* w      = (const float*)d_in[5];
    const float* plas   = (const float*)d_in[6];
    const float* learn  = (const float*)d_in[7];
    const float* W_h2o  = (const float*)d_in[8];
    const float* b_h2o  = (const float*)d_in[9];

    float* out      = (float*)d_out;
    float* x_out    = out + OUT;
    float* hebb_out = out + OUT + H;

    dim3 g1(NJ8 / 256, GY);   // (2, 296) = 592 blocks = one wave at occ 4
    k_recur<<<g1, 256>>>(hidden, hebb, w, plas);

    k_reduce<<<NJ4 / 8, 256>>>(inp, W_i2h, b_i2h, x_out);

    int n4 = (H * H) / 4;
    k_hebb_out<<<n4 / 256, 256>>>(hidden, hebb, learn, W_h2o, b_h2o,
                                  hebb_out, out);
}